// round 9
// baseline (speedup 1.0000x reference)
#include <cuda_runtime.h>

// SNN: B=1024, T=4096, 6 -> 10 -> 27 LIF (subtract reset).
// TWO warps per batch element (2048 warps -> 4/SMSP on 128 SMs):
//   A-warp: phaseA (x@W1+b1, f32x2), layer-1 recurrence, ballots -> SMEM masks
//   B-warp: one chunk behind, table[msk] lookups, layer-2 recurrence, output
// One __syncthreads per 32-step chunk is the only cross-warp ordering.

#define T_LEN 4096
#define BETA 0.9f
#define CTA_THREADS 512
#define N_CTAS 128
#define EPC 8 /* elements per CTA; warps 0..7 = A, 8..15 = B */

#define ZERO_ROW 1024u
#define TABLE_FLOATS (1024 * 27 + 32)   /* row 1024 = zeros */
#define STG_STRIDE 14                    /* even: aligned 64-bit stores; reads conflict-free */
#define STG_BANK 468                     /* >= 31*14+31+1 */
#define STG_PER_ELEM (2 * STG_BANK)
#define STG_TOTAL (EPC * STG_PER_ELEM)
#define MASK_TOTAL (EPC * 64)            /* [elem][2 banks][32 steps] */
#define SMEM_FLOATS (TABLE_FLOATS + STG_TOTAL + MASK_TOTAL)
#define SMEM_BYTES (SMEM_FLOATS * 4)     /* 127,744 B */

typedef unsigned long long u64;

__device__ __forceinline__ u64 pack2(float lo, float hi) {
    u64 r; asm("mov.b64 %0,{%1,%2};" : "=l"(r) : "f"(lo), "f"(hi)); return r;
}
__device__ __forceinline__ u64 mul2(u64 a, u64 b) {
    u64 r; asm("mul.rn.f32x2 %0,%1,%2;" : "=l"(r) : "l"(a), "l"(b)); return r;
}
__device__ __forceinline__ u64 fma2(u64 a, u64 b, u64 c) {
    u64 r; asm("fma.rn.f32x2 %0,%1,%2,%3;" : "=l"(r) : "l"(a), "l"(b), "l"(c)); return r;
}
__device__ __forceinline__ u64 add2(u64 a, u64 b) {
    u64 r; asm("add.rn.f32x2 %0,%1,%2;" : "=l"(r) : "l"(a), "l"(b)); return r;
}
// float 1.0f/0.0f from comparison, fixed-latency, no predicate on the chain
__device__ __forceinline__ float fset_gt1(float a) {
    float r; asm("set.gt.f32.f32 %0,%1,0f3F800000;" : "=f"(r) : "f"(a)); return r;
}

// Phase A: 10 neuron currents for this lane's timestep, f32x2-packed.
// Per-half rounding == scalar ops; ascending-k FFMA chain from a mul, then +b1
// == cublas accumulation order (reference-exact).
__device__ __forceinline__ void phaseA_store(const float xv[6],
                                             const u64 w12r[5][6],
                                             const u64 b12r[5],
                                             float* wb, int lane)
{
    u64 xx[6];
#pragma unroll
    for (int c = 0; c < 6; c++) xx[c] = pack2(xv[c], xv[c]);
#pragma unroll
    for (int np = 0; np < 5; np++) {
        u64 a = mul2(xx[0], w12r[np][0]);
#pragma unroll
        for (int c = 1; c < 6; c++)
            a = fma2(xx[c], w12r[np][c], a);
        a = add2(a, b12r[np]);
        *reinterpret_cast<u64*>(&wb[lane * STG_STRIDE + 2 * np]) = a;
    }
}

__global__ void __launch_bounds__(CTA_THREADS, 1)
snn_kernel(const float* __restrict__ x, const float* __restrict__ W1,
           const float* __restrict__ b1, const float* __restrict__ W2,
           const float* __restrict__ b2, float* __restrict__ out)
{
    extern __shared__ float smem[];
    float* table = smem;                                   // [1024][27] + zero row
    float* stg   = smem + TABLE_FLOATS;                    // [EPC][2][32 x STG_STRIDE]
    unsigned* maskbuf = (unsigned*)(smem + TABLE_FLOATS + STG_TOTAL); // [EPC][2][32]

    const int tid  = threadIdx.x;
    const int wid  = tid >> 5;
    const int lane = tid & 31;

    // ---- init: layer-2 table (ascending-n accumulation == reference fma-dot
    // with 0/1 spikes; adding 0.0f is exact) + zero pad row + mask prefill.
    for (int e = tid; e < 1024 * 27; e += CTA_THREADS) {
        int v = e / 27;
        int m = e - v * 27;
        float acc = 0.0f;
#pragma unroll
        for (int n = 0; n < 10; n++)
            if (v & (1 << n)) acc = __fadd_rn(acc, W2[m * 10 + n]);
        table[e] = __fadd_rn(acc, b2[m]);
    }
    for (int i = 1024 * 27 + tid; i < TABLE_FLOATS; i += CTA_THREADS)
        table[i] = 0.0f;                       // ZERO_ROW
    for (int i = tid; i < MASK_TOTAL; i += CTA_THREADS)
        maskbuf[i] = ZERO_ROW;                 // fake chunk "-1": zero currents

    const bool isA = (wid < EPC);
    const int  e   = isA ? wid : wid - EPC;
    const int  b   = blockIdx.x * EPC + e;

    const float* xb   = x + (size_t)b * (6 * T_LEN);
    const float* trow = table + lane;
    float* stA = stg + e * STG_PER_ELEM;
    unsigned* mbase = maskbuf + e * 64;

    // A-warp state
    u64 w12r[5][6], b12r[5];
    float xv[6];
    float m1 = 0.0f, s1 = 0.0f;
    // B-warp state
    float m2 = 0.0f, s2 = 0.0f;

    if (isA) {
#pragma unroll
        for (int np = 0; np < 5; np++) {
            b12r[np] = pack2(b1[2 * np], b1[2 * np + 1]);
#pragma unroll
            for (int c = 0; c < 6; c++)
                w12r[np][c] = pack2(W1[(2 * np) * 6 + c], W1[(2 * np + 1) * 6 + c]);
        }
#pragma unroll
        for (int c = 0; c < 6; c++) xv[c] = xb[c * T_LEN + lane];
        phaseA_store(xv, w12r, b12r, stA, lane);   // chunk 0 -> bank 0
#pragma unroll
        for (int c = 0; c < 6; c++) xv[c] = xb[c * T_LEN + 32 + lane];
    }
    __syncthreads();  // table + prefill + chunk-0 staging visible

    const bool vlane = (lane < 10);

#pragma unroll 1
    for (int k = 0; k < 128; k++) {
        if (isA) {
            // ---- A: layer-1 chunk k; phaseA for k+1; masks -> bank k&1
            const float* rb = stA + (k & 1) * STG_BANK;
            float* wb = stA + ((k + 1) & 1) * STG_BANK;
            if (k < 127)
                phaseA_store(xv, w12r, b12r, wb, lane);
            {
                int kk = (k + 2 < 128) ? k + 2 : 127;  // clamped prefetch
#pragma unroll
                for (int c = 0; c < 6; c++)
                    xv[c] = xb[c * T_LEN + kk * 32 + lane];
            }
            unsigned* mrow = mbase + (k & 1) * 32;
#pragma unroll
            for (int sb = 0; sb < 4; sb++) {
                float c1r[8];
#pragma unroll
                for (int i = 0; i < 8; i++)
                    c1r[i] = rb[(sb * 8 + i) * STG_STRIDE + lane];
#pragma unroll
                for (int i = 0; i < 8; i++) {
                    // reference: mem = fma(beta,mem,cur) - rst ; rst in {0,1}
                    float a1 = fmaf(BETA, m1, c1r[i]);
                    m1 = __fsub_rn(a1, s1);
                    s1 = fset_gt1(m1);
                    // lanes >=10 hold garbage (unwritten staging cols) -> masked
                    mrow[sb * 8 + i] =
                        __ballot_sync(0xffffffffu, (m1 > 1.0f) && vlane);
                }
            }
        } else {
            // ---- B: layer-2 chunk k-1 (bank (k-1)&1 == (k+1)&1)
            const unsigned* mrow = mbase + ((k + 1) & 1) * 32;
#pragma unroll
            for (int sb = 0; sb < 4; sb++) {
                unsigned mb[8];
                float c2[8];
#pragma unroll
                for (int i = 0; i < 8; i++) mb[i] = mrow[sb * 8 + i]; // broadcast
#pragma unroll
                for (int i = 0; i < 8; i++) c2[i] = trow[mb[i] * 27u];
#pragma unroll
                for (int i = 0; i < 8; i++) {
                    float a2 = fmaf(BETA, m2, c2[i]);
                    m2 = __fsub_rn(a2, s2);
                    s2 = fset_gt1(m2);
                }
            }
        }
        __syncthreads();  // masks/staging of this iter visible next iter
    }

    // Epilogue: B processes chunk 127 (bank 1) and writes the output spike.
    if (!isA) {
        const unsigned* mrow = mbase + 32;
#pragma unroll
        for (int sb = 0; sb < 4; sb++) {
            unsigned mb[8];
            float c2[8];
#pragma unroll
            for (int i = 0; i < 8; i++) mb[i] = mrow[sb * 8 + i];
#pragma unroll
            for (int i = 0; i < 8; i++) c2[i] = trow[mb[i] * 27u];
#pragma unroll
            for (int i = 0; i < 8; i++) {
                float a2 = fmaf(BETA, m2, c2[i]);
                m2 = __fsub_rn(a2, s2);
                s2 = fset_gt1(m2);
            }
        }
        if (lane < 27)
            out[b * 27 + lane] = s2;
    }
}

extern "C" void kernel_launch(void* const* d_in, const int* in_sizes, int n_in,
                              void* d_out, int out_size)
{
    const float* x  = (const float*)d_in[0];
    const float* W1 = (const float*)d_in[1];
    const float* b1 = (const float*)d_in[2];
    const float* W2 = (const float*)d_in[3];
    const float* b2 = (const float*)d_in[4];
    float* out = (float*)d_out;

    cudaFuncSetAttribute(snn_kernel, cudaFuncAttributeMaxDynamicSharedMemorySize,
                         SMEM_BYTES);

    snn_kernel<<<N_CTAS, CTA_THREADS, SMEM_BYTES>>>(x, W1, b1, W2, b2, out);
}

// round 11
// speedup vs baseline: 1.2539x; 1.2539x over previous
#include <cuda_runtime.h>

// SNN: B=1024, T=4096, 6 -> 10 -> 27 LIF (subtract reset).
// TWO batch elements per warp, warp-private pipeline (no CTA barriers in loop):
//   L1 SIMD-packed: lanes 0-9 = elem0 neurons, 16-25 = elem1 neurons
//   one ballot/step serves both elements (masks extracted as bitfields)
//   layer-2: 2 table lookups + 2 small recurrences per lane (lanes 0-26)
// 512 warps as 4/CTA x 128 CTAs (1 warp/SMSP, all SMs), 255-reg budget.
// Sink discipline: sub-batched (4-step) LDS/vote/fetch pipeline, L2 lag 9.
// R11 fix: TABLE_FLOATS padded to even -> staging 8B-aligned for STS.64.

#define T_LEN 4096
#define BETA 0.9f
#define CTA_THREADS 128
#define N_CTAS 128

#define ZERO_ROW 1024u
#define TABLE_FLOATS 27712               /* 1025*27=27675 data, padded to %4==0 */
#define STG_STRIDE 34                    /* even: aligned STS.64, conflict-free */
#define STG_BANK (32 * STG_STRIDE)
#define STG_PER_WARP (2 * STG_BANK)
#define SMEM_FLOATS (TABLE_FLOATS + 4 * STG_PER_WARP)
#define SMEM_BYTES (SMEM_FLOATS * 4)     /* 145,664 B */

typedef unsigned long long u64;

__device__ __forceinline__ u64 pack2(float lo, float hi) {
    u64 r; asm("mov.b64 %0,{%1,%2};" : "=l"(r) : "f"(lo), "f"(hi)); return r;
}
__device__ __forceinline__ u64 mul2(u64 a, u64 b) {
    u64 r; asm("mul.rn.f32x2 %0,%1,%2;" : "=l"(r) : "l"(a), "l"(b)); return r;
}
__device__ __forceinline__ u64 fma2(u64 a, u64 b, u64 c) {
    u64 r; asm("fma.rn.f32x2 %0,%1,%2,%3;" : "=l"(r) : "l"(a), "l"(b), "l"(c)); return r;
}
__device__ __forceinline__ u64 add2(u64 a, u64 b) {
    u64 r; asm("add.rn.f32x2 %0,%1,%2;" : "=l"(r) : "l"(a), "l"(b)); return r;
}
__device__ __forceinline__ float fset_gt1(float a) {
    float r; asm("set.gt.f32.f32 %0,%1,0f3F800000;" : "=f"(r) : "f"(a)); return r;
}

// Phase A for ONE element into staging cols [base, base+10).
// Per-half f32x2 rounding == scalar; ascending-k chain from a mul, then +b1
// == cublas accumulation order (reference-exact).
__device__ __forceinline__ void phaseA_store(const float xv[6],
                                             const u64 w12r[5][6],
                                             const u64 b12r[5],
                                             float* wb, int lane, int base)
{
    u64 xx[6];
#pragma unroll
    for (int c = 0; c < 6; c++) xx[c] = pack2(xv[c], xv[c]);
#pragma unroll
    for (int np = 0; np < 5; np++) {
        u64 a = mul2(xx[0], w12r[np][0]);
#pragma unroll
        for (int c = 1; c < 6; c++)
            a = fma2(xx[c], w12r[np][c], a);
        a = add2(a, b12r[np]);
        *reinterpret_cast<u64*>(&wb[lane * STG_STRIDE + base + 2 * np]) = a;
    }
}

// One 32-step chunk = 8 sub-batches of 4. Vote is of the PREVIOUS step's pred;
// fetch uses masks one sub-batch old; L2 lags L1 by 9 steps.
__device__ __forceinline__ void fused_chunk(const float* rb, int lane,
                                            const float* trow,
                                            float& m1, float& s1,
                                            float& m20, float& s20,
                                            float& m21, float& s21,
                                            bool& pd, bool vlane,
                                            unsigned (&msk)[2][4],
                                            float (&c20)[2][4],
                                            float (&c21)[2][4])
{
#pragma unroll
    for (int sb = 0; sb < 8; sb++) {
        const int p = sb & 1, q = p ^ 1;

        float c1r[4];
#pragma unroll
        for (int i = 0; i < 4; i++)
            c1r[i] = rb[(sb * 4 + i) * STG_STRIDE + lane];
        // fetch currents for previous sub-batch's masks (votes long drained);
        // consumed only next sub-batch (LDS long drained). Bit 10 of each
        // field is only ever the fictitious init bit -> index 1024 (zeros).
#pragma unroll
        for (int i = 0; i < 4; i++) {
            unsigned v = msk[q][i];
            c20[p][i] = trow[(v & 0x7FFu) * 27u];
            c21[p][i] = trow[((v >> 16) & 0x7FFu) * 27u];
        }
#pragma unroll
        for (int i = 0; i < 4; i++) {
            msk[p][i] = __ballot_sync(0xffffffffu, pd);  // lagged pred: no stall

            // layer 1 (both elems SIMD): mem = fma(beta,mem,cur) - s;
            // s = (mem>1) as float via FSET (reference-exact values).
            float a1 = fmaf(BETA, m1, c1r[i]);
            m1 = __fsub_rn(a1, s1);
            s1 = fset_gt1(m1);
            pd = (m1 > 1.0f) && vlane;  // sink until next iteration's ballot

            // layer 2, elem0 and elem1 (independent 8-cyc chains)
            float a2 = fmaf(BETA, m20, c20[q][i]);
            m20 = __fsub_rn(a2, s20);
            s20 = fset_gt1(m20);
            float a3 = fmaf(BETA, m21, c21[q][i]);
            m21 = __fsub_rn(a3, s21);
            s21 = fset_gt1(m21);
        }
    }
}

__global__ void __launch_bounds__(CTA_THREADS, 1)
snn_kernel(const float* __restrict__ x, const float* __restrict__ W1,
           const float* __restrict__ b1, const float* __restrict__ W2,
           const float* __restrict__ b2, float* __restrict__ out)
{
    extern __shared__ float smem[];
    float* table = smem;                 // rows 0..1023 real; row 1024 zeros
    float* stg   = smem + TABLE_FLOATS;  // [4 warps][2 banks][32 x 34], 16B-aligned

    const int tid  = threadIdx.x;
    const int warp = tid >> 5;
    const int lane = tid & 31;
    const int b0 = (blockIdx.x * 4 + warp) * 2;
    const int b1i = b0 + 1;

    const float* xb0 = x + (size_t)b0 * (6 * T_LEN);
    const float* xb1 = x + (size_t)b1i * (6 * T_LEN);

    // kick off chunk-0 x loads under the table build
    float xv0[6], xv1[6];
#pragma unroll
    for (int c = 0; c < 6; c++) {
        xv0[c] = xb0[c * T_LEN + lane];
        xv1[c] = xb1[c * T_LEN + lane];
    }

    // Layer-2 lookup table: ascending-n accumulation == reference fma-dot
    // with 0/1 spikes (adding 0.0f is exact).
    for (int e = tid; e < 1024 * 27; e += CTA_THREADS) {
        int v = e / 27;
        int m = e - v * 27;
        float acc = 0.0f;
#pragma unroll
        for (int n = 0; n < 10; n++)
            if (v & (1 << n)) acc = __fadd_rn(acc, W2[m * 10 + n]);
        table[e] = __fadd_rn(acc, b2[m]);
    }
    for (int i = 1024 * 27 + tid; i < TABLE_FLOATS; i += CTA_THREADS)
        table[i] = 0.0f;  // ZERO_ROW (row 1024) + pad
    __syncthreads();

    u64 w12r[5][6], b12r[5];
#pragma unroll
    for (int np = 0; np < 5; np++) {
        b12r[np] = pack2(b1[2 * np], b1[2 * np + 1]);
#pragma unroll
        for (int c = 0; c < 6; c++)
            w12r[np][c] = pack2(W1[(2 * np) * 6 + c], W1[(2 * np + 1) * 6 + c]);
    }

    float* bank0 = stg + warp * STG_PER_WARP;
    float* bank1 = bank0 + STG_BANK;
    const float* trow = table + lane;

    // lanes 0-9: elem0 neurons; 16-25: elem1 neurons; others garbage (masked)
    const bool vlane = (lane < 10) || (lane >= 16 && lane < 26);
    float m1 = 0.0f, s1 = 0.0f;
    float m20 = 0.0f, s20 = 0.0f, m21 = 0.0f, s21 = 0.0f;
    // fictitious step -1 pred -> ballot = (1<<10)|(1<<26) -> both idx = 1024
    bool pd = (lane == 10) || (lane == 26);
    unsigned msk[2][4];
    float c20[2][4], c21[2][4];
#pragma unroll
    for (int i = 0; i < 4; i++) {
        msk[0][i] = (1u << 10) | (1u << 26);
        msk[1][i] = (1u << 10) | (1u << 26);
        c20[0][i] = 0.0f; c20[1][i] = 0.0f;
        c21[0][i] = 0.0f; c21[1][i] = 0.0f;
    }

    // Prologue: phaseA(ch0) -> bank0; xv <- ch1.
    phaseA_store(xv0, w12r, b12r, bank0, lane, 0);
    phaseA_store(xv1, w12r, b12r, bank0, lane, 16);
#pragma unroll
    for (int c = 0; c < 6; c++) {
        xv0[c] = xb0[c * T_LEN + 32 + lane];
        xv1[c] = xb1[c * T_LEN + 32 + lane];
    }
    __syncwarp();

#pragma unroll 1
    for (int k = 0; k < 128; k++) {
        const float* rb = (k & 1) ? bank1 : bank0;
        float* wb = (k & 1) ? bank0 : bank1;
        if (k < 127) {
            phaseA_store(xv0, w12r, b12r, wb, lane, 0);
            phaseA_store(xv1, w12r, b12r, wb, lane, 16);
        }
        {
            int kk = (k + 2 < 128) ? k + 2 : 127;  // clamped prefetch
#pragma unroll
            for (int c = 0; c < 6; c++) {
                xv0[c] = xb0[c * T_LEN + kk * 32 + lane];
                xv1[c] = xb1[c * T_LEN + kk * 32 + lane];
            }
        }
        fused_chunk(rb, lane, trow, m1, s1, m20, s20, m21, s21,
                    pd, vlane, msk, c20, c21);
        __syncwarp();
    }

    // Epilogue: L2 lags 9 steps. Last sub-batch parity p=1.
    // (1) consume c2*[1] (4 steps, fetched during the last sub-batch)
#pragma unroll
    for (int i = 0; i < 4; i++) {
        float a2 = fmaf(BETA, m20, c20[1][i]);
        m20 = __fsub_rn(a2, s20); s20 = fset_gt1(m20);
        float a3 = fmaf(BETA, m21, c21[1][i]);
        m21 = __fsub_rn(a3, s21); s21 = fset_gt1(m21);
    }
    // (2) fetch + consume msk[1] (4 steps)
#pragma unroll
    for (int i = 0; i < 4; i++) {
        unsigned v = msk[1][i];
        float f0 = trow[(v & 0x7FFu) * 27u];
        float f1 = trow[((v >> 16) & 0x7FFu) * 27u];
        float a2 = fmaf(BETA, m20, f0);
        m20 = __fsub_rn(a2, s20); s20 = fset_gt1(m20);
        float a3 = fmaf(BETA, m21, f1);
        m21 = __fsub_rn(a3, s21); s21 = fset_gt1(m21);
    }
    // (3) final step's mask is in pd
    {
        unsigned v = __ballot_sync(0xffffffffu, pd);
        float f0 = trow[(v & 0x7FFu) * 27u];
        float f1 = trow[((v >> 16) & 0x7FFu) * 27u];
        float a2 = fmaf(BETA, m20, f0);
        m20 = __fsub_rn(a2, s20); s20 = fset_gt1(m20);
        float a3 = fmaf(BETA, m21, f1);
        m21 = __fsub_rn(a3, s21); s21 = fset_gt1(m21);
    }

    if (lane < 27) {
        out[b0 * 27 + lane] = s20;
        out[b1i * 27 + lane] = s21;
    }
}

extern "C" void kernel_launch(void* const* d_in, const int* in_sizes, int n_in,
                              void* d_out, int out_size)
{
    const float* x  = (const float*)d_in[0];
    const float* W1 = (const float*)d_in[1];
    const float* b1 = (const float*)d_in[2];
    const float* W2 = (const float*)d_in[3];
    const float* b2 = (const float*)d_in[4];
    float* out = (float*)d_out;

    cudaFuncSetAttribute(snn_kernel, cudaFuncAttributeMaxDynamicSharedMemorySize,
                         SMEM_BYTES);

    snn_kernel<<<N_CTAS, CTA_THREADS, SMEM_BYTES>>>(x, W1, b1, W2, b2, out);
}

// round 12
// speedup vs baseline: 1.6270x; 1.2976x over previous
#include <cuda_runtime.h>

// SNN: B=1024, T=4096, 6 -> 10 -> 27 LIF (subtract reset).
// Producer/consumer WARP PAIRS, one element per pair, per-pair named barriers:
//   A-warp: layer-1 recurrence + lagged ballot; masks -> SMEM (STS.128 / 4 steps)
//   B-warp: phaseA staging for A, mask LDS.128, table fetch, layer-2, output
// 16 warps/CTA x 128 CTAs = 2048 warps = 4/SMSP on all 128 SMs.
// Sync: bar.sync(1+pair, 64) once per 32-step chunk; no CTA barriers in loop.

#define T_LEN 4096
#define BETA 0.9f
#define CTA_THREADS 512
#define N_CTAS 128
#define PAIRS 8

#define TABLE_FLOATS (1024 * 27 + 32)  /* 27680; rows 0..1023 + zero row 1024 */
#define ZERO_ROW 1024u
#define STG_STRIDE 14
#define STG_BANK 480                    /* >= 31*14+31+1, 16B-mult */
#define STG_PER_PAIR (2 * STG_BANK)
#define MB_BANK 36                      /* u32: 32 masks + extra + pad (16B mult) */
#define MB_PER_PAIR (2 * MB_BANK)
#define MASK_U32 (PAIRS * MB_PER_PAIR)  /* 576 */
#define SMEM_FLOATS (TABLE_FLOATS + MASK_U32 + PAIRS * STG_PER_PAIR)
#define SMEM_BYTES (SMEM_FLOATS * 4)    /* 143,744 B */

typedef unsigned long long u64;

__device__ __forceinline__ u64 pack2(float lo, float hi) {
    u64 r; asm("mov.b64 %0,{%1,%2};" : "=l"(r) : "f"(lo), "f"(hi)); return r;
}
__device__ __forceinline__ u64 mul2(u64 a, u64 b) {
    u64 r; asm("mul.rn.f32x2 %0,%1,%2;" : "=l"(r) : "l"(a), "l"(b)); return r;
}
__device__ __forceinline__ u64 fma2(u64 a, u64 b, u64 c) {
    u64 r; asm("fma.rn.f32x2 %0,%1,%2,%3;" : "=l"(r) : "l"(a), "l"(b), "l"(c)); return r;
}
__device__ __forceinline__ u64 add2(u64 a, u64 b) {
    u64 r; asm("add.rn.f32x2 %0,%1,%2;" : "=l"(r) : "l"(a), "l"(b)); return r;
}
__device__ __forceinline__ float fset_gt1(float a) {
    float r; asm("set.gt.f32.f32 %0,%1,0f3F800000;" : "=f"(r) : "f"(a)); return r;
}
#define PAIR_BAR(pid) asm volatile("bar.sync %0, 64;" :: "r"(1 + (pid)) : "memory")

// Phase A: 10 neuron currents for one timestep (this lane's), f32x2-packed.
// Per-half rounding == scalar; ascending-k chain from a mul, then +b1
// == cublas accumulation order (reference-exact).
__device__ __forceinline__ void phaseA_store(const float xv[6],
                                             const u64 w12r[5][6],
                                             const u64 b12r[5],
                                             float* wb, int lane)
{
    u64 xx[6];
#pragma unroll
    for (int c = 0; c < 6; c++) xx[c] = pack2(xv[c], xv[c]);
#pragma unroll
    for (int np = 0; np < 5; np++) {
        u64 a = mul2(xx[0], w12r[np][0]);
#pragma unroll
        for (int c = 1; c < 6; c++)
            a = fma2(xx[c], w12r[np][c], a);
        a = add2(a, b12r[np]);
        *reinterpret_cast<u64*>(&wb[lane * STG_STRIDE + 2 * np]) = a;
    }
}

// 4 layer-2 steps: mem = fma(beta,mem,cur) - s ; s = (mem>1) as float.
__device__ __forceinline__ void l2_consume4(const float c[4], float& m2, float& s2)
{
#pragma unroll
    for (int i = 0; i < 4; i++) {
        float a2 = fmaf(BETA, m2, c[i]);
        m2 = __fsub_rn(a2, s2);
        s2 = fset_gt1(m2);
    }
}

__global__ void __launch_bounds__(CTA_THREADS, 1)
snn_kernel(const float* __restrict__ x, const float* __restrict__ W1,
           const float* __restrict__ b1, const float* __restrict__ W2,
           const float* __restrict__ b2, float* __restrict__ out)
{
    extern __shared__ float smem[];
    float* table = smem;                                  // [1024][27] + zero row
    unsigned* maskall = (unsigned*)(smem + TABLE_FLOATS); // [PAIRS][2][36]
    float* stg = smem + TABLE_FLOATS + MASK_U32;          // [PAIRS][2][480]

    const int tid  = threadIdx.x;
    const int wid  = tid >> 5;
    const int lane = tid & 31;
    const bool isA = (wid < PAIRS);
    const int pair = wid & (PAIRS - 1);
    const int b = blockIdx.x * PAIRS + pair;

    const float* xb = x + (size_t)b * (6 * T_LEN);

    // Layer-2 lookup table: ascending-n accumulation == reference fma-dot
    // with 0/1 spikes (adding 0.0f is exact).
    for (int e = tid; e < 1024 * 27; e += CTA_THREADS) {
        int v = e / 27;
        int m = e - v * 27;
        float acc = 0.0f;
#pragma unroll
        for (int n = 0; n < 10; n++)
            if (v & (1 << n)) acc = __fadd_rn(acc, W2[m * 10 + n]);
        table[e] = __fadd_rn(acc, b2[m]);
    }
    for (int i = 1024 * 27 + tid; i < TABLE_FLOATS; i += CTA_THREADS)
        table[i] = 0.0f;  // ZERO_ROW (row 1024)

    unsigned* mbase = maskall + pair * MB_PER_PAIR;
    float* stg0 = stg + pair * STG_PER_PAIR;
    float* stg1 = stg0 + STG_BANK;

    if (isA) {
        // ================= A-warp: layer 1 producer =================
        __syncthreads();  // table + B's phaseA(0) staging visible

        float m1 = 0.0f, s1 = 0.0f;
        bool pd = (lane == 10);        // ballot(step -1) = 1<<10 = ZERO_ROW
        const bool vlane = (lane < 10);
        const bool st_lane = (lane == 0);

#pragma unroll 1
        for (int k = 0; k < 128; k++) {
            const float* rb = (k & 1) ? stg1 : stg0;
            unsigned* mrow = mbase + (k & 1) * MB_BANK;
#pragma unroll
            for (int sb = 0; sb < 8; sb++) {
                float c1r[4];
#pragma unroll
                for (int i = 0; i < 4; i++)
                    c1r[i] = rb[(sb * 4 + i) * STG_STRIDE + lane];
                unsigned mr[4];
#pragma unroll
                for (int i = 0; i < 4; i++) {
                    mr[i] = __ballot_sync(0xffffffffu, pd);  // lagged: no stall
                    float a1 = fmaf(BETA, m1, c1r[i]);
                    m1 = __fsub_rn(a1, s1);
                    s1 = fset_gt1(m1);
                    pd = (m1 > 1.0f) && vlane;  // sink until next ballot
                }
                if (st_lane)
                    *reinterpret_cast<uint4*>(mrow + sb * 4) =
                        make_uint4(mr[0], mr[1], mr[2], mr[3]);
            }
            PAIR_BAR(pair);
        }
        // final mask (step 4095) -> bank1 extra slot
        unsigned vf = __ballot_sync(0xffffffffu, pd);
        if (st_lane) mbase[MB_BANK + 32] = vf;
        PAIR_BAR(pair);
    } else {
        // ================= B-warp: phaseA + layer 2 consumer =================
        u64 w12r[5][6], b12r[5];
#pragma unroll
        for (int np = 0; np < 5; np++) {
            b12r[np] = pack2(b1[2 * np], b1[2 * np + 1]);
#pragma unroll
            for (int c = 0; c < 6; c++)
                w12r[np][c] = pack2(W1[(2 * np) * 6 + c], W1[(2 * np + 1) * 6 + c]);
        }
        float xv[6];
#pragma unroll
        for (int c = 0; c < 6; c++) xv[c] = xb[c * T_LEN + lane];
        phaseA_store(xv, w12r, b12r, stg0, lane);  // chunk 0 -> bank 0
#pragma unroll
        for (int c = 0; c < 6; c++) xv[c] = xb[c * T_LEN + 32 + lane];

        __syncthreads();

        const float* trow = table + lane;
        float m2 = 0.0f, s2 = 0.0f;
        float carry[4] = {0.0f, 0.0f, 0.0f, 0.0f};  // 4 fake zero steps (exact)

#pragma unroll 1
        for (int k = 0; k < 128; k++) {
            // phaseA for chunk k+1 into the other bank; prefetch x
            if (k < 127) {
                float* wb = ((k + 1) & 1) ? stg1 : stg0;
                phaseA_store(xv, w12r, b12r, wb, lane);
                int kk = (k + 2 < 128) ? k + 2 : 127;
#pragma unroll
                for (int c = 0; c < 6; c++)
                    xv[c] = xb[c * T_LEN + kk * 32 + lane];
            }
            if (k >= 1) {
                const unsigned* mrow = mbase + ((k - 1) & 1) * MB_BANK;
                uint4 cur = *reinterpret_cast<const uint4*>(mrow);
#pragma unroll
                for (int sb = 0; sb < 8; sb++) {
                    uint4 nxt = cur;
                    if (sb < 7)
                        nxt = *reinterpret_cast<const uint4*>(mrow + (sb + 1) * 4);
                    float f[4];
                    f[0] = trow[cur.x * 27u];
                    f[1] = trow[cur.y * 27u];
                    f[2] = trow[cur.z * 27u];
                    f[3] = trow[cur.w * 27u];
                    l2_consume4(carry, m2, s2);
#pragma unroll
                    for (int i = 0; i < 4; i++) carry[i] = f[i];
                    cur = nxt;
                }
            }
            PAIR_BAR(pair);
        }
        PAIR_BAR(pair);  // A's final mask + bank1 masks visible

        // Epilogue: chunk 127 (bank 1) + final mask (slot 32)
        {
            const unsigned* mrow = mbase + MB_BANK;
            uint4 cur = *reinterpret_cast<const uint4*>(mrow);
#pragma unroll
            for (int sb = 0; sb < 8; sb++) {
                uint4 nxt = cur;
                if (sb < 7)
                    nxt = *reinterpret_cast<const uint4*>(mrow + (sb + 1) * 4);
                float f[4];
                f[0] = trow[cur.x * 27u];
                f[1] = trow[cur.y * 27u];
                f[2] = trow[cur.z * 27u];
                f[3] = trow[cur.w * 27u];
                l2_consume4(carry, m2, s2);
#pragma unroll
                for (int i = 0; i < 4; i++) carry[i] = f[i];
                cur = nxt;
            }
            float ff = trow[mrow[32] * 27u];  // mask(4095)
            l2_consume4(carry, m2, s2);
            float a2 = fmaf(BETA, m2, ff);
            m2 = __fsub_rn(a2, s2);
            s2 = fset_gt1(m2);
        }

        if (lane < 27)
            out[b * 27 + lane] = s2;
    }
}

extern "C" void kernel_launch(void* const* d_in, const int* in_sizes, int n_in,
                              void* d_out, int out_size)
{
    const float* x  = (const float*)d_in[0];
    const float* W1 = (const float*)d_in[1];
    const float* b1 = (const float*)d_in[2];
    const float* W2 = (const float*)d_in[3];
    const float* b2 = (const float*)d_in[4];
    float* out = (float*)d_out;

    cudaFuncSetAttribute(snn_kernel, cudaFuncAttributeMaxDynamicSharedMemorySize,
                         SMEM_BYTES);

    snn_kernel<<<N_CTAS, CTA_THREADS, SMEM_BYTES>>>(x, W1, b1, W2, b2, out);
}